// round 17
// baseline (speedup 1.0000x reference)
#include <cuda_runtime.h>
#include <math.h>

typedef unsigned long long ull;

#define N_CELLS 131072
#define IN_D 64
#define HID_D 128
#define OUT_D 64
#define GIN 65              // OUT_D + 1
#define NF 8
#define FS (N_CELLS / NF)   // 16384
#define DC (FS / 4)         // 4096

#define CELLS 32
#define HALF 16
#define MT 256
#define NCTAS (N_CELLS / CELLS)   // 4096
#define SH 36               // padded cell-minor row stride (floats)

// ---------------- packed f32x2 helpers (Blackwell FFMA2) --------------------
__device__ __forceinline__ ull ffma2(ull a, ull b, ull c) {
    ull d;
    asm("fma.rn.f32x2 %0, %1, %2, %3;" : "=l"(d) : "l"(a), "l"(b), "l"(c));
    return d;
}
__device__ __forceinline__ ull pack2(float v) {
    ull d;
    asm("mov.b64 %0, {%1, %1};" : "=l"(d) : "f"(v));
    return d;
}
__device__ __forceinline__ float2 unpk(ull u) {
    float lo, hi;
    asm("mov.b64 {%0, %1}, %2;" : "=f"(lo), "=f"(hi) : "l"(u));
    return make_float2(lo, hi);
}

// ------------------------- device scratch (no runtime alloc) ----------------
__device__ float2 g_W1I[HID_D * HID_D];      // (wa,wg) h-part, k*128+j
__device__ float  g_hb1a[HID_D];             // b1a + W1a_x @ x (x folded)
__device__ float  g_hb1g[HID_D];
__device__ float  g_W2aT[HID_D * OUT_D];     // j*64+o
__device__ float  g_W2gT[HID_D * OUT_D];
__device__ float  g_b2d[OUT_D];              // b2a - b2g
__device__ float2 g_WiRZ[GIN * HID_D];       // (wr,wz) at k*128+d
__device__ float  g_WiN[GIN * HID_D];
__device__ float2 g_WhRZ[HID_D * HID_D];
__device__ float  g_WhN[HID_D * HID_D];
__device__ float  g_gb[4 * HID_D];
__device__ float  g_fsum[NF * HID_D];
__device__ float  g_fm[NF * HID_D];
__device__ float  g_go[HID_D];
__device__ float  g_wsum[OUT_D];
__device__ float  g_sumexp;
__device__ float  g_tsum;

// ------------------------- prep: fold/transpose weights ---------------------
__global__ void prep_kernel(const float* __restrict__ x,
                            const float* __restrict__ W1a, const float* __restrict__ b1a,
                            const float* __restrict__ W1g, const float* __restrict__ b1g,
                            const float* __restrict__ W2a, const float* __restrict__ b2a,
                            const float* __restrict__ W2g, const float* __restrict__ b2g,
                            const float* __restrict__ Wih, const float* __restrict__ Whh,
                            const float* __restrict__ bih, const float* __restrict__ bhh) {
    int i = blockIdx.x * blockDim.x + threadIdx.x;
    int stride = gridDim.x * blockDim.x;
    const int CD = IN_D + HID_D;  // 192
    for (int idx = i; idx < HID_D * HID_D; idx += stride) {
        int k = idx >> 7, j = idx & 127;
        g_W1I[idx] = make_float2(W1a[j * CD + IN_D + k], W1g[j * CD + IN_D + k]);
    }
    for (int idx = i; idx < 2 * HID_D; idx += stride) {
        int j = idx & 127, eng = idx >> 7;
        const float* W = eng ? W1g : W1a;
        float acc = eng ? b1g[j] : b1a[j];
        for (int k = 0; k < IN_D; k++) acc = fmaf(W[j * CD + k], x[k], acc);
        if (eng) g_hb1g[j] = acc; else g_hb1a[j] = acc;
    }
    for (int idx = i; idx < HID_D * OUT_D; idx += stride) {
        int j = idx >> 6, o = idx & 63;
        g_W2aT[idx] = W2a[o * HID_D + j];
        g_W2gT[idx] = W2g[o * HID_D + j];
    }
    for (int idx = i; idx < OUT_D; idx += stride) {
        g_b2d[idx] = b2a[idx] - b2g[idx];
        g_wsum[idx] = 0.f;
    }
    for (int idx = i; idx < GIN * HID_D; idx += stride) {
        int k = idx >> 7, d = idx & 127;
        g_WiRZ[idx] = make_float2(Wih[d * GIN + k], Wih[(HID_D + d) * GIN + k]);
        g_WiN[idx]  = Wih[(2 * HID_D + d) * GIN + k];
    }
    for (int idx = i; idx < HID_D * HID_D; idx += stride) {
        int k = idx >> 7, d = idx & 127;
        g_WhRZ[idx] = make_float2(Whh[d * HID_D + k], Whh[(HID_D + d) * HID_D + k]);
        g_WhN[idx]  = Whh[(2 * HID_D + d) * HID_D + k];
    }
    for (int idx = i; idx < HID_D; idx += stride) {
        g_gb[idx]             = bih[idx] + bhh[idx];
        g_gb[HID_D + idx]     = bih[HID_D + idx] + bhh[HID_D + idx];
        g_gb[2 * HID_D + idx] = bih[2 * HID_D + idx];
        g_gb[3 * HID_D + idx] = bhh[2 * HID_D + idx];
    }
    for (int idx = i; idx < NF * HID_D; idx += stride) g_fsum[idx] = 0.f;
    if (i == 0) { g_sumexp = 0.f; g_tsum = 0.f; }
}

// ------------------------- dynamic smem layout (floats) ---------------------
#define OFF_H    0                           // sh_h   [128][SH]  18 KB
#define OFF_HID  (OFF_H + HID_D * SH)        // sh_hid [256][SH]  36 KB
#define OFF_OT   (OFF_HID + 2 * HID_D * SH)  // sh_oT  [65][SH]   9.1 KB
#define OFF_E    (OFF_OT + GIN * SH)         // sh_e   [32]
#define SMEM_FLOATS (OFF_E + CELLS)
#define SMEM_BYTES  (SMEM_FLOATS * 4)        // ~63.3 KB -> 3 CTAs/SM

// ------------------------- main fused per-cell kernel -----------------------
__global__ void __launch_bounds__(MT, 3) main_kernel(
    const float* __restrict__ hiddens, float* __restrict__ newh_out)
{
    extern __shared__ __align__(16) float smem[];
    float* sh_h   = smem + OFF_H;
    float* sh_hid = smem + OFF_HID;
    float* sh_oT  = smem + OFF_OT;
    float* sh_e   = smem + OFF_E;

    const int tid = threadIdx.x;
    const int n0 = blockIdx.x * CELLS;

    // ---- load h transposed (cell-minor, padded rows) ----
    #pragma unroll
    for (int it = 0; it < CELLS * HID_D / MT; it++) {
        int idx = tid + it * MT;
        int m = idx >> 7, d = idx & 127;
        sh_h[d * SH + m] = hiddens[(size_t)(n0 + m) * HID_D + d];
    }
    __syncthreads();

    const int lane128 = tid & 127, half = tid >> 7, cb = half * HALF;

    // ---- phase 1: hidden1 = relu(h @ W1h^T + folded bias) ----
    {
        const int j = lane128;
        ull a2[8], g2[8];
        #pragma unroll
        for (int q = 0; q < 8; q++) { a2[q] = 0ull; g2[q] = 0ull; }
        #pragma unroll 4
        for (int k = 0; k < HID_D; k++) {
            float2 w = g_W1I[k * HID_D + j];
            ull wa2 = pack2(w.x), wg2 = pack2(w.y);
            const float* vp = sh_h + k * SH + cb;
            #pragma unroll
            for (int q = 0; q < 4; q++) {
                ulonglong2 v = *(const ulonglong2*)(vp + q * 4);
                a2[2 * q]     = ffma2(wa2, v.x, a2[2 * q]);
                a2[2 * q + 1] = ffma2(wa2, v.y, a2[2 * q + 1]);
                g2[2 * q]     = ffma2(wg2, v.x, g2[2 * q]);
                g2[2 * q + 1] = ffma2(wg2, v.y, g2[2 * q + 1]);
            }
        }
        float ba = g_hb1a[j], bg = g_hb1g[j];
        float* pa = sh_hid + j * SH + cb;
        float* pg = sh_hid + (HID_D + j) * SH + cb;
        #pragma unroll
        for (int q = 0; q < 8; q++) {
            float2 av = unpk(a2[q]), gv = unpk(g2[q]);
            *(float2*)(pa + 2 * q) = make_float2(fmaxf(av.x + ba, 0.f), fmaxf(av.y + ba, 0.f));
            *(float2*)(pg + 2 * q) = make_float2(fmaxf(gv.x + bg, 0.f), fmaxf(gv.y + bg, 0.f));
        }
    }
    __syncthreads();

    // ---- phase 2: layer2, a/g halves in parallel, in-place a-g into sh_oT ----
    {
        const int o = tid & 63, part = (tid >> 6) & 1;
        const float* W2T = part ? g_W2gT : g_W2aT;
        const float* hid = sh_hid + part * HID_D * SH + cb;
        ull acc[8];
        #pragma unroll
        for (int q = 0; q < 8; q++) acc[q] = 0ull;
        #pragma unroll 4
        for (int jj = 0; jj < HID_D; jj++) {
            ull w2 = pack2(W2T[jj * OUT_D + o]);
            const float* vp = hid + jj * SH;
            #pragma unroll
            for (int q = 0; q < 4; q++) {
                ulonglong2 v = *(const ulonglong2*)(vp + q * 4);
                acc[2 * q]     = ffma2(w2, v.x, acc[2 * q]);
                acc[2 * q + 1] = ffma2(w2, v.y, acc[2 * q + 1]);
            }
        }
        float* po = sh_oT + o * SH + cb;
        if (part == 0) {   // a-half stores first
            #pragma unroll
            for (int q = 0; q < 8; q++) {
                float2 p = unpk(acc[q]);
                po[2 * q]     = p.x;
                po[2 * q + 1] = p.y;
            }
        }
        __syncthreads();
        if (part == 1) {   // g-half subtracts in place, adds bias diff
            float bd = g_b2d[o];
            #pragma unroll
            for (int q = 0; q < 8; q++) {
                float2 p = unpk(acc[q]);
                po[2 * q]     = po[2 * q]     - p.x + bd;
                po[2 * q + 1] = po[2 * q + 1] - p.y + bd;
            }
        }
    }
    __syncthreads();

    // ---- tension + exp (shift-invariant softmax: no max subtraction) ----
    if (tid < CELLS) {
        int b = tid;
        float s = 0.f;
        #pragma unroll
        for (int o = 0; o < OUT_D; o++) { float v = sh_oT[o * SH + b]; s = fmaf(v, v, s); }
        float tv = s * (1.0f / OUT_D);
        sh_oT[(GIN - 1) * SH + b] = tv;   // GRU input column 64
        float e = expf(tv);
        sh_e[b] = e;
        float es = e, ts = tv;
        #pragma unroll
        for (int off = 16; off > 0; off >>= 1) {
            es += __shfl_down_sync(0xffffffffu, es, off);
            ts += __shfl_down_sync(0xffffffffu, ts, off);
        }
        if (b == 0) {
            atomicAdd(&g_sumexp, es);
            atomicAdd(&g_tsum, ts);
        }
    }
    __syncthreads();

    // ---- softmax numerator partial: wsum_o += sum_b e_b * out[b][o] ----
    if (tid < OUT_D) {
        const int o = tid;
        const float* po = sh_oT + o * SH;
        float acc = 0.f;
        #pragma unroll 4
        for (int b = 0; b < CELLS; b++)
            acc = fmaf(sh_e[b], po[b], acc);
        atomicAdd(&g_wsum[o], acc);
    }

    // ---- phase 3: GRU, 2 passes of 8 cells (32 accum regs -> 3 CTAs/SM) ----
    {
        const int d = lane128;
        const float gb_r = g_gb[d], gb_z = g_gb[HID_D + d];
        const float gb_n = g_gb[2 * HID_D + d], gb_h = g_gb[3 * HID_D + d];
        float fsum_local = 0.f;
        #pragma unroll
        for (int p = 0; p < 2; p++) {
            const int cbb = cb + p * 8;
            ull r2[4], z2[4], n2[4], hn2[4];
            {
                ull br = pack2(gb_r), bz = pack2(gb_z), bn = pack2(gb_n), bh = pack2(gb_h);
                #pragma unroll
                for (int q = 0; q < 4; q++) { r2[q] = br; z2[q] = bz; n2[q] = bn; hn2[q] = bh; }
            }
            #pragma unroll 2
            for (int k = 0; k < GIN; k++) {
                float2 wrz = g_WiRZ[k * HID_D + d];
                float  wn  = g_WiN[k * HID_D + d];
                ull wr2 = pack2(wrz.x), wz2 = pack2(wrz.y), wn2 = pack2(wn);
                const float* vp = sh_oT + k * SH + cbb;
                #pragma unroll
                for (int q = 0; q < 2; q++) {
                    ulonglong2 v = *(const ulonglong2*)(vp + q * 4);
                    r2[2 * q]     = ffma2(wr2, v.x, r2[2 * q]);
                    r2[2 * q + 1] = ffma2(wr2, v.y, r2[2 * q + 1]);
                    z2[2 * q]     = ffma2(wz2, v.x, z2[2 * q]);
                    z2[2 * q + 1] = ffma2(wz2, v.y, z2[2 * q + 1]);
                    n2[2 * q]     = ffma2(wn2, v.x, n2[2 * q]);
                    n2[2 * q + 1] = ffma2(wn2, v.y, n2[2 * q + 1]);
                }
            }
            #pragma unroll 2
            for (int k = 0; k < HID_D; k++) {
                float2 wrz = g_WhRZ[k * HID_D + d];
                float  wn  = g_WhN[k * HID_D + d];
                ull wr2 = pack2(wrz.x), wz2 = pack2(wrz.y), wn2 = pack2(wn);
                const float* vp = sh_h + k * SH + cbb;
                #pragma unroll
                for (int q = 0; q < 2; q++) {
                    ulonglong2 v = *(const ulonglong2*)(vp + q * 4);
                    r2[2 * q]      = ffma2(wr2, v.x, r2[2 * q]);
                    r2[2 * q + 1]  = ffma2(wr2, v.y, r2[2 * q + 1]);
                    z2[2 * q]      = ffma2(wz2, v.x, z2[2 * q]);
                    z2[2 * q + 1]  = ffma2(wz2, v.y, z2[2 * q + 1]);
                    hn2[2 * q]     = ffma2(wn2, v.x, hn2[2 * q]);
                    hn2[2 * q + 1] = ffma2(wn2, v.y, hn2[2 * q + 1]);
                }
            }
            float* nout = newh_out + (size_t)(n0 + cbb) * HID_D + d;
            const float* hsrc = sh_h + d * SH + cbb;
            #pragma unroll
            for (int q = 0; q < 4; q++) {
                float2 rf = unpk(r2[q]), zf = unpk(z2[q]);
                float2 inn = unpk(n2[q]), hnf = unpk(hn2[q]);
                {
                    float r = 1.f / (1.f + expf(-rf.x));
                    float z = 1.f / (1.f + expf(-zf.x));
                    float nn = tanhf(inn.x + r * hnf.x);
                    float nh = (1.f - z) * nn + z * hsrc[2 * q];
                    fsum_local += nh;
                    nout[(size_t)(2 * q) * HID_D] = nh;
                }
                {
                    float r = 1.f / (1.f + expf(-rf.y));
                    float z = 1.f / (1.f + expf(-zf.y));
                    float nn = tanhf(inn.y + r * hnf.y);
                    float nh = (1.f - z) * nn + z * hsrc[2 * q + 1];
                    fsum_local += nh;
                    nout[(size_t)(2 * q + 1) * HID_D] = nh;
                }
            }
        }
        int f = blockIdx.x / (FS / CELLS);   // one faction per CTA
        atomicAdd(&g_fsum[f * HID_D + d], fsum_local);
    }
}

// ---------------- faction means + global opinion + output head ---------------
__global__ void post_kernel(const float* __restrict__ Wo, const float* __restrict__ bo,
                            float* __restrict__ out) {
    int t = threadIdx.x;  // 128
    {   // faction means / global opinion (independent of head work)
        int d = t;
        float s = 0.f;
        #pragma unroll
        for (int f = 0; f < NF; f++) {
            float fm = g_fsum[f * HID_D + d] * (1.0f / FS);
            g_fm[f * HID_D + d] = fm;
            s += fm;
        }
        g_go[d] = s * (1.0f / NF);
    }
    if (t < OUT_D) {
        int i = t;
        float inv = 1.f / g_sumexp;
        float acc = bo[i];
        #pragma unroll 4
        for (int j = 0; j < OUT_D; j++)
            acc = fmaf(g_wsum[j] * inv, Wo[i * OUT_D + j], acc);
        out[i] = acc;
        if (i == 0) out[OUT_D] = g_tsum * (1.0f / N_CELLS);
    }
}

// ------------------------- faction sync finalize (scalar, in place) ----------
// NOTE: newh is d_out + 65 floats (260 B) -> NOT 16B-aligned; scalar access only.
__global__ void __launch_bounds__(256) finalize_kernel(float* __restrict__ newh,
                                                       const int* __restrict__ step) {
    int idx = blockIdx.x * blockDim.x + threadIdx.x;  // < N_CELLS * HID_D
    int n = idx >> 7, d = idx & 127;
    float pre = newh[idx];
    int f = n >> 14;  // FS == 16384
    float v = 0.85f * pre + 0.15f * g_fm[f * HID_D + d];
    if (*step > 5 && (n & (FS - 1)) < DC)
        v = 0.85f * v + 0.15f * g_go[d];
    newh[idx] = v;
}

// ------------------------- launch ---------------------------------------------
extern "C" void kernel_launch(void* const* d_in, const int* in_sizes, int n_in,
                              void* d_out, int out_size) {
    const float* x       = (const float*)d_in[0];
    const float* hiddens = (const float*)d_in[1];
    const float* W1a = (const float*)d_in[2];  const float* b1a = (const float*)d_in[3];
    const float* W2a = (const float*)d_in[4];  const float* b2a = (const float*)d_in[5];
    const float* W1g = (const float*)d_in[6];  const float* b1g = (const float*)d_in[7];
    const float* W2g = (const float*)d_in[8];  const float* b2g = (const float*)d_in[9];
    const float* Wih = (const float*)d_in[10]; const float* Whh = (const float*)d_in[11];
    const float* bih = (const float*)d_in[12]; const float* bhh = (const float*)d_in[13];
    const float* Wo  = (const float*)d_in[14]; const float* bo  = (const float*)d_in[15];
    const int*   step = (const int*)d_in[16];

    float* out = (float*)d_out;
    float* newh = out + OUT_D + 1;  // [pred(64) | t.mean(1) | new_h(131072*128)]

    cudaFuncSetAttribute(main_kernel, cudaFuncAttributeMaxDynamicSharedMemorySize, SMEM_BYTES);

    prep_kernel<<<128, 256>>>(x, W1a, b1a, W1g, b1g, W2a, b2a, W2g, b2g,
                              Wih, Whh, bih, bhh);
    main_kernel<<<NCTAS, MT, SMEM_BYTES>>>(hiddens, newh);
    post_kernel<<<1, HID_D>>>(Wo, bo, out);
    finalize_kernel<<<(N_CELLS * HID_D) / 256, 256>>>(newh, step);
}